// round 1
// baseline (speedup 1.0000x reference)
#include <cuda_runtime.h>
#include <cuda_bf16.h>

#define BHALF 4096
#define NROW  8192
#define DIM   256
#define INV_T (1.0f/0.07f)
#define LOG2E 1.4426950408889634f

#define TILE_M 128
#define TILE_N 128
#define SM_STRIDE 264            // 256 + 8 bf16 pad -> conflict-free fragment loads
#define SMEM_BYTES (2 * TILE_M * SM_STRIDE * 2)   // 135168 B

__device__ __nv_bfloat16 g_zn[NROW * DIM];   // normalized rows, bf16 (4 MB)
__device__ float g_sumexp[NROW];
__device__ float g_pos[NROW];

// ---------------------------------------------------------------------------
// Kernel A: L2-normalize rows of concat(z_i, z_j) -> bf16; zero accumulators
// ---------------------------------------------------------------------------
__global__ void normalize_kernel(const float* __restrict__ z_i,
                                 const float* __restrict__ z_j) {
    int row = blockIdx.x;
    const float* src = (row < BHALF) ? (z_i + (size_t)row * DIM)
                                     : (z_j + (size_t)(row - BHALF) * DIM);
    int tid = threadIdx.x;  // 64 threads, 4 elems each
    float4 v = ((const float4*)src)[tid];
    float ss = v.x * v.x + v.y * v.y + v.z * v.z + v.w * v.w;
    #pragma unroll
    for (int o = 16; o; o >>= 1) ss += __shfl_xor_sync(0xffffffffu, ss, o);
    __shared__ float sw[2];
    if ((tid & 31) == 0) sw[tid >> 5] = ss;
    __syncthreads();
    float nrm = sqrtf(sw[0] + sw[1]);
    nrm = fmaxf(nrm, 1e-8f);
    float inv = 1.0f / nrm;
    __nv_bfloat16* dst = g_zn + (size_t)row * DIM + tid * 4;
    dst[0] = __float2bfloat16(v.x * inv);
    dst[1] = __float2bfloat16(v.y * inv);
    dst[2] = __float2bfloat16(v.z * inv);
    dst[3] = __float2bfloat16(v.w * inv);
    if (tid == 0) { g_sumexp[row] = 0.0f; g_pos[row] = 0.0f; }
}

// ---------------------------------------------------------------------------
// fast exp(v) via 2^y, FMA-pipe only (MUFU would bottleneck at 0.5 op/cyc/SM)
// input y = v * log2(e); |y| <= ~21 here, so the exponent trick is safe.
// ---------------------------------------------------------------------------
__device__ __forceinline__ float fast_exp2(float y) {
    float t  = y + 12582912.0f;          // round-to-nearest-int trick (1.5*2^23)
    int   i  = __float_as_int(t);        // low bits hold n (two's complement)
    float nf = t - 12582912.0f;
    float f  = y - nf;                   // f in [-0.5, 0.5]
    float p  = fmaf(1.3333558e-3f, f, 9.6181291e-3f);
    p = fmaf(p, f, 5.5504109e-2f);
    p = fmaf(p, f, 2.4022651e-1f);
    p = fmaf(p, f, 6.9314718e-1f);
    p = fmaf(p, f, 1.0f);
    // 2^n: (i<<23) drops the 0x4B400000 bias bits exactly; add fp32 exp bias
    return p * __int_as_float((i << 23) + 0x3F800000);
}

__device__ __forceinline__ void mma16816(float c[4],
                                         unsigned a0, unsigned a1, unsigned a2, unsigned a3,
                                         unsigned b0, unsigned b1) {
    asm volatile(
        "mma.sync.aligned.m16n8k16.row.col.f32.bf16.bf16.f32 "
        "{%0,%1,%2,%3}, {%4,%5,%6,%7}, {%8,%9}, {%0,%1,%2,%3};\n"
        : "+f"(c[0]), "+f"(c[1]), "+f"(c[2]), "+f"(c[3])
        : "r"(a0), "r"(a1), "r"(a2), "r"(a3), "r"(b0), "r"(b1));
}

// ---------------------------------------------------------------------------
// Kernel B: bf16 GEMM (zn @ zn^T) with fused exp + diagonal mask + row sums
// grid: (64 row-tiles, 4 column slices of 2048)
// ---------------------------------------------------------------------------
__global__ void __launch_bounds__(256, 1) ntxent_gemm_kernel() {
    extern __shared__ __nv_bfloat16 smem[];
    __nv_bfloat16* As = smem;
    __nv_bfloat16* Bs = smem + TILE_M * SM_STRIDE;

    int tid  = threadIdx.x;
    int warp = tid >> 5, lane = tid & 31;
    int g    = lane >> 2, tig = lane & 3;
    int wm   = warp >> 2, wn = warp & 3;      // 2x4 warp grid -> 64x32 per warp

    int rowbase  = blockIdx.x * TILE_M;
    int colbase0 = blockIdx.y * (NROW / 4);

    // Load A tile once (128 x 256 bf16)
    {
        const uint4* gsrc = (const uint4*)(g_zn + (size_t)rowbase * DIM);
        #pragma unroll
        for (int idx = tid; idx < TILE_M * DIM / 8; idx += 256) {
            int r = idx >> 5, c8 = idx & 31;
            *(uint4*)(As + r * SM_STRIDE + c8 * 8) = gsrc[r * 32 + c8];
        }
    }

    float rsum[4][2];
    #pragma unroll
    for (int mt = 0; mt < 4; mt++) { rsum[mt][0] = 0.f; rsum[mt][1] = 0.f; }

    for (int t = 0; t < 16; t++) {
        int colbase = colbase0 + t * TILE_N;

        __syncthreads();   // previous tile's compute done (and A stores visible)
        {
            const uint4* gsrc = (const uint4*)(g_zn + (size_t)colbase * DIM);
            #pragma unroll
            for (int idx = tid; idx < TILE_N * DIM / 8; idx += 256) {
                int r = idx >> 5, c8 = idx & 31;
                *(uint4*)(Bs + r * SM_STRIDE + c8 * 8) = gsrc[r * 32 + c8];
            }
        }
        __syncthreads();

        float acc[4][4][4];
        #pragma unroll
        for (int mt = 0; mt < 4; mt++)
            #pragma unroll
            for (int nt = 0; nt < 4; nt++)
                #pragma unroll
                for (int ci = 0; ci < 4; ci++) acc[mt][nt][ci] = 0.f;

        #pragma unroll
        for (int kk = 0; kk < 16; kk++) {
            int k0 = kk * 16 + tig * 2;
            unsigned a[4][4], b[4][2];
            #pragma unroll
            for (int mt = 0; mt < 4; mt++) {
                const __nv_bfloat16* ap = As + (wm * 64 + mt * 16 + g) * SM_STRIDE + k0;
                a[mt][0] = *(const unsigned*)(ap);
                a[mt][1] = *(const unsigned*)(ap + 8 * SM_STRIDE);
                a[mt][2] = *(const unsigned*)(ap + 8);
                a[mt][3] = *(const unsigned*)(ap + 8 * SM_STRIDE + 8);
            }
            #pragma unroll
            for (int nt = 0; nt < 4; nt++) {
                const __nv_bfloat16* bp = Bs + (wn * 32 + nt * 8 + g) * SM_STRIDE + k0;
                b[nt][0] = *(const unsigned*)(bp);
                b[nt][1] = *(const unsigned*)(bp + 8);
            }
            #pragma unroll
            for (int mt = 0; mt < 4; mt++)
                #pragma unroll
                for (int nt = 0; nt < 4; nt++)
                    mma16816(acc[mt][nt], a[mt][0], a[mt][1], a[mt][2], a[mt][3],
                             b[nt][0], b[nt][1]);
        }

        // Fused epilogue: exp + mask + positive-logit capture + row-sum
        bool hasDiag = (colbase == rowbase);
        bool hasPos  = (colbase == ((rowbase + BHALF) & (NROW - 1)));
        if (hasDiag || hasPos) {
            #pragma unroll
            for (int mt = 0; mt < 4; mt++) {
                int row0 = rowbase + wm * 64 + mt * 16 + g;
                #pragma unroll
                for (int nt = 0; nt < 4; nt++) {
                    int col0 = colbase + wn * 32 + nt * 8 + tig * 2;
                    #pragma unroll
                    for (int ci = 0; ci < 4; ci++) {
                        int row = row0 + (ci >> 1) * 8;
                        int col = col0 + (ci & 1);
                        float v = acc[mt][nt][ci];
                        float e = fast_exp2(v * (INV_T * LOG2E));
                        if (col == ((row + BHALF) & (NROW - 1)))
                            g_pos[row] = v * INV_T;
                        if (col == row) e = 0.0f;   // exact diagonal mask
                        rsum[mt][ci >> 1] += e;
                    }
                }
            }
        } else {
            #pragma unroll
            for (int mt = 0; mt < 4; mt++) {
                #pragma unroll
                for (int nt = 0; nt < 4; nt++) {
                    #pragma unroll
                    for (int ci = 0; ci < 4; ci++) {
                        float e = fast_exp2(acc[mt][nt][ci] * (INV_T * LOG2E));
                        rsum[mt][ci >> 1] += e;
                    }
                }
            }
        }
    }

    // Reduce row sums across the 4 lanes (tig) sharing each row, then global
    #pragma unroll
    for (int mt = 0; mt < 4; mt++) {
        #pragma unroll
        for (int h = 0; h < 2; h++) {
            float v = rsum[mt][h];
            v += __shfl_xor_sync(0xffffffffu, v, 1);
            v += __shfl_xor_sync(0xffffffffu, v, 2);
            if (tig == 0) {
                int row = rowbase + wm * 64 + mt * 16 + g + h * 8;
                atomicAdd(&g_sumexp[row], v);
            }
        }
    }
}

// ---------------------------------------------------------------------------
// Kernel C: loss = mean_k( log(sumexp_k) - pos_k )
// ---------------------------------------------------------------------------
__global__ void loss_kernel(float* __restrict__ out) {
    int tid = threadIdx.x;  // 1024
    float s = 0.0f;
    for (int k = tid; k < NROW; k += 1024)
        s += logf(g_sumexp[k]) - g_pos[k];
    #pragma unroll
    for (int o = 16; o; o >>= 1) s += __shfl_xor_sync(0xffffffffu, s, o);
    __shared__ float sw[32];
    if ((tid & 31) == 0) sw[tid >> 5] = s;
    __syncthreads();
    if (tid < 32) {
        float v = sw[tid];
        #pragma unroll
        for (int o = 16; o; o >>= 1) v += __shfl_xor_sync(0xffffffffu, v, o);
        if (tid == 0) out[0] = v / (float)NROW;
    }
}

extern "C" void kernel_launch(void* const* d_in, const int* in_sizes, int n_in,
                              void* d_out, int out_size) {
    const float* z_i = (const float*)d_in[0];
    const float* z_j = (const float*)d_in[1];
    float* out = (float*)d_out;

    cudaFuncSetAttribute(ntxent_gemm_kernel,
                         cudaFuncAttributeMaxDynamicSharedMemorySize, SMEM_BYTES);

    normalize_kernel<<<NROW, 64>>>(z_i, z_j);
    ntxent_gemm_kernel<<<dim3(64, 4), 256, SMEM_BYTES>>>();
    loss_kernel<<<1, 1024>>>(out);
}

// round 2
// speedup vs baseline: 1.6062x; 1.6062x over previous
#include <cuda_runtime.h>
#include <cuda_bf16.h>

#define BHALF 4096
#define NROW  8192
#define DIM   256
#define INV_T (1.0f/0.07f)
#define LOG2E 1.4426950408889634f

#define TILE_M 128
#define TILE_N 128
#define SM_STRIDE 264            // 256 + 8 bf16 pad -> conflict-free fragment loads
#define SMEM_BYTES (2 * TILE_M * SM_STRIDE * 2)   // 135168 B

__device__ __nv_bfloat16 g_zn[NROW * DIM];   // normalized rows, bf16 (4 MB)
__device__ float g_sumexp[NROW];
__device__ float g_pos[NROW];

// ---------------------------------------------------------------------------
// Kernel A: L2-normalize rows of concat(z_i, z_j) -> bf16; zero accumulators
// one warp per row; 8 rows per 256-thread block
// ---------------------------------------------------------------------------
__global__ void normalize_kernel(const float* __restrict__ z_i,
                                 const float* __restrict__ z_j) {
    int warp = threadIdx.x >> 5, lane = threadIdx.x & 31;
    int row  = blockIdx.x * 8 + warp;
    const float* src = (row < BHALF) ? (z_i + (size_t)row * DIM)
                                     : (z_j + (size_t)(row - BHALF) * DIM);
    float4 v0 = ((const float4*)src)[lane * 2];
    float4 v1 = ((const float4*)src)[lane * 2 + 1];
    float ss = v0.x*v0.x + v0.y*v0.y + v0.z*v0.z + v0.w*v0.w
             + v1.x*v1.x + v1.y*v1.y + v1.z*v1.z + v1.w*v1.w;
    #pragma unroll
    for (int o = 16; o; o >>= 1) ss += __shfl_xor_sync(0xffffffffu, ss, o);
    float inv = 1.0f / fmaxf(sqrtf(ss), 1e-8f);

    __nv_bfloat162 h0 = __floats2bfloat162_rn(v0.x*inv, v0.y*inv);
    __nv_bfloat162 h1 = __floats2bfloat162_rn(v0.z*inv, v0.w*inv);
    __nv_bfloat162 h2 = __floats2bfloat162_rn(v1.x*inv, v1.y*inv);
    __nv_bfloat162 h3 = __floats2bfloat162_rn(v1.z*inv, v1.w*inv);
    uint4 u;
    u.x = *(unsigned*)&h0; u.y = *(unsigned*)&h1;
    u.z = *(unsigned*)&h2; u.w = *(unsigned*)&h3;
    *(uint4*)(g_zn + (size_t)row * DIM + lane * 8) = u;
    if (lane == 0) { g_sumexp[row] = 0.0f; g_pos[row] = 0.0f; }
}

// ---------------------------------------------------------------------------
// fast exp via 2^y on the FMA pipe (MUFU would bottleneck at 0.5 op/cyc/SM)
// ---------------------------------------------------------------------------
__device__ __forceinline__ float fast_exp2(float y) {
    float t  = y + 12582912.0f;          // round-to-nearest-int trick (1.5*2^23)
    int   i  = __float_as_int(t);
    float nf = t - 12582912.0f;
    float f  = y - nf;                   // f in [-0.5, 0.5]
    float p  = fmaf(1.3333558e-3f, f, 9.6181291e-3f);
    p = fmaf(p, f, 5.5504109e-2f);
    p = fmaf(p, f, 2.4022651e-1f);
    p = fmaf(p, f, 6.9314718e-1f);
    p = fmaf(p, f, 1.0f);
    return p * __int_as_float((i << 23) + 0x3F800000);
}

__device__ __forceinline__ void mma16816(float c[4],
                                         unsigned a0, unsigned a1, unsigned a2, unsigned a3,
                                         unsigned b0, unsigned b1) {
    asm volatile(
        "mma.sync.aligned.m16n8k16.row.col.f32.bf16.bf16.f32 "
        "{%0,%1,%2,%3}, {%4,%5,%6,%7}, {%8,%9}, {%0,%1,%2,%3};\n"
        : "+f"(c[0]), "+f"(c[1]), "+f"(c[2]), "+f"(c[3])
        : "r"(a0), "r"(a1), "r"(a2), "r"(a3), "r"(b0), "r"(b1));
}

// ---------------------------------------------------------------------------
// Kernel B: symmetric bf16 GEMM (upper-triangle tiles only) with fused
// exp + diagonal mask + row AND column sum-of-exp (sim is symmetric)
// grid: (64 row-tiles, 4 column slices); tiles with j < i skipped
// ---------------------------------------------------------------------------
__global__ void __launch_bounds__(256, 1) ntxent_gemm_kernel() {
    extern __shared__ __nv_bfloat16 smem[];
    __nv_bfloat16* As = smem;
    __nv_bfloat16* Bs = smem + TILE_M * SM_STRIDE;

    int tid  = threadIdx.x;
    int warp = tid >> 5, lane = tid & 31;
    int g    = lane >> 2, tig = lane & 3;
    int wm   = warp >> 2, wn = warp & 3;      // 2x4 warp grid -> 64x32 per warp

    int iTile   = blockIdx.x;
    int rowbase = iTile * TILE_M;

    // Load A tile once (128 x 256 bf16)
    {
        const uint4* gsrc = (const uint4*)(g_zn + (size_t)rowbase * DIM);
        #pragma unroll
        for (int idx = tid; idx < TILE_M * DIM / 8; idx += 256) {
            int r = idx >> 5, c8 = idx & 31;
            *(uint4*)(As + r * SM_STRIDE + c8 * 8) = gsrc[r * 32 + c8];
        }
    }

    float rsum[4][2];
    #pragma unroll
    for (int mt = 0; mt < 4; mt++) { rsum[mt][0] = 0.f; rsum[mt][1] = 0.f; }

    bool didWork = false;

    for (int t = 0; t < 16; t++) {
        int jTile = blockIdx.y * 16 + t;
        if (jTile < iTile) continue;          // symmetry: upper triangle only
        didWork = true;
        int colbase = jTile * TILE_M;

        __syncthreads();   // previous tile's compute done (and A stores visible)
        {
            const uint4* gsrc = (const uint4*)(g_zn + (size_t)colbase * DIM);
            #pragma unroll
            for (int idx = tid; idx < TILE_N * DIM / 8; idx += 256) {
                int r = idx >> 5, c8 = idx & 31;
                *(uint4*)(Bs + r * SM_STRIDE + c8 * 8) = gsrc[r * 32 + c8];
            }
        }
        __syncthreads();

        float acc[4][4][4];
        #pragma unroll
        for (int mt = 0; mt < 4; mt++)
            #pragma unroll
            for (int nt = 0; nt < 4; nt++)
                #pragma unroll
                for (int ci = 0; ci < 4; ci++) acc[mt][nt][ci] = 0.f;

        #pragma unroll
        for (int kk = 0; kk < 16; kk++) {
            int k0 = kk * 16 + tig * 2;
            unsigned a[4][4], b[4][2];
            #pragma unroll
            for (int mt = 0; mt < 4; mt++) {
                const __nv_bfloat16* ap = As + (wm * 64 + mt * 16 + g) * SM_STRIDE + k0;
                a[mt][0] = *(const unsigned*)(ap);
                a[mt][1] = *(const unsigned*)(ap + 8 * SM_STRIDE);
                a[mt][2] = *(const unsigned*)(ap + 8);
                a[mt][3] = *(const unsigned*)(ap + 8 * SM_STRIDE + 8);
            }
            #pragma unroll
            for (int nt = 0; nt < 4; nt++) {
                const __nv_bfloat16* bp = Bs + (wn * 32 + nt * 8 + g) * SM_STRIDE + k0;
                b[nt][0] = *(const unsigned*)(bp);
                b[nt][1] = *(const unsigned*)(bp + 8);
            }
            #pragma unroll
            for (int mt = 0; mt < 4; mt++)
                #pragma unroll
                for (int nt = 0; nt < 4; nt++)
                    mma16816(acc[mt][nt], a[mt][0], a[mt][1], a[mt][2], a[mt][3],
                             b[nt][0], b[nt][1]);
        }

        if (jTile == iTile) {
            // Diagonal tile: row sums only (tile covers its own transpose),
            // with exact diagonal mask.
            #pragma unroll
            for (int mt = 0; mt < 4; mt++) {
                int row0 = rowbase + wm * 64 + mt * 16 + g;
                #pragma unroll
                for (int nt = 0; nt < 4; nt++) {
                    int col0 = colbase + wn * 32 + nt * 8 + tig * 2;
                    #pragma unroll
                    for (int ci = 0; ci < 4; ci++) {
                        int row = row0 + (ci >> 1) * 8;
                        int col = col0 + (ci & 1);
                        float e = fast_exp2(acc[mt][nt][ci] * (INV_T * LOG2E));
                        if (col == row) e = 0.0f;
                        rsum[mt][ci >> 1] += e;
                    }
                }
            }
        } else {
            // Off-diagonal tile: each element serves row AND (by symmetry) col.
            float csum[4][2];
            #pragma unroll
            for (int nt = 0; nt < 4; nt++) { csum[nt][0] = 0.f; csum[nt][1] = 0.f; }

            bool hasPos = (jTile == iTile + 32);   // contains sim[r, r+4096]
            if (hasPos) {
                #pragma unroll
                for (int mt = 0; mt < 4; mt++) {
                    int row0 = rowbase + wm * 64 + mt * 16 + g;
                    #pragma unroll
                    for (int nt = 0; nt < 4; nt++) {
                        int col0 = colbase + wn * 32 + nt * 8 + tig * 2;
                        #pragma unroll
                        for (int ci = 0; ci < 4; ci++) {
                            int row = row0 + (ci >> 1) * 8;
                            int col = col0 + (ci & 1);
                            float v = acc[mt][nt][ci];
                            float e = fast_exp2(v * (INV_T * LOG2E));
                            if (col == row + BHALF) {      // positive pair (both dirs)
                                g_pos[row] = v * INV_T;
                                g_pos[col] = v * INV_T;
                            }
                            rsum[mt][ci >> 1] += e;
                            csum[nt][ci & 1]  += e;
                        }
                    }
                }
            } else {
                #pragma unroll
                for (int mt = 0; mt < 4; mt++) {
                    #pragma unroll
                    for (int nt = 0; nt < 4; nt++) {
                        #pragma unroll
                        for (int ci = 0; ci < 4; ci++) {
                            float e = fast_exp2(acc[mt][nt][ci] * (INV_T * LOG2E));
                            rsum[mt][ci >> 1] += e;
                            csum[nt][ci & 1]  += e;
                        }
                    }
                }
            }

            // Column reduction: sum over g lanes (xor 4,8,16), then atomic.
            #pragma unroll
            for (int nt = 0; nt < 4; nt++) {
                #pragma unroll
                for (int p = 0; p < 2; p++) {
                    float v = csum[nt][p];
                    v += __shfl_xor_sync(0xffffffffu, v, 4);
                    v += __shfl_xor_sync(0xffffffffu, v, 8);
                    v += __shfl_xor_sync(0xffffffffu, v, 16);
                    if (g == 0) {
                        int col = colbase + wn * 32 + nt * 8 + tig * 2 + p;
                        atomicAdd(&g_sumexp[col], v);
                    }
                }
            }
        }
    }

    if (!didWork) return;

    // Reduce row sums across the 4 lanes (tig) sharing each row, then global
    #pragma unroll
    for (int mt = 0; mt < 4; mt++) {
        #pragma unroll
        for (int h = 0; h < 2; h++) {
            float v = rsum[mt][h];
            v += __shfl_xor_sync(0xffffffffu, v, 1);
            v += __shfl_xor_sync(0xffffffffu, v, 2);
            if (tig == 0) {
                int row = rowbase + wm * 64 + mt * 16 + g + h * 8;
                atomicAdd(&g_sumexp[row], v);
            }
        }
    }
}

// ---------------------------------------------------------------------------
// Kernel C: loss = mean_k( log(sumexp_k) - pos_k )
// ---------------------------------------------------------------------------
__global__ void loss_kernel(float* __restrict__ out) {
    int tid = threadIdx.x;  // 1024
    float s = 0.0f;
    for (int k = tid; k < NROW; k += 1024)
        s += logf(g_sumexp[k]) - g_pos[k];
    #pragma unroll
    for (int o = 16; o; o >>= 1) s += __shfl_xor_sync(0xffffffffu, s, o);
    __shared__ float sw[32];
    if ((tid & 31) == 0) sw[tid >> 5] = s;
    __syncthreads();
    if (tid < 32) {
        float v = sw[tid];
        #pragma unroll
        for (int o = 16; o; o >>= 1) v += __shfl_xor_sync(0xffffffffu, v, o);
        if (tid == 0) out[0] = v / (float)NROW;
    }
}

extern "C" void kernel_launch(void* const* d_in, const int* in_sizes, int n_in,
                              void* d_out, int out_size) {
    const float* z_i = (const float*)d_in[0];
    const float* z_j = (const float*)d_in[1];
    float* out = (float*)d_out;

    cudaFuncSetAttribute(ntxent_gemm_kernel,
                         cudaFuncAttributeMaxDynamicSharedMemorySize, SMEM_BYTES);

    normalize_kernel<<<NROW / 8, 256>>>(z_i, z_j);
    ntxent_gemm_kernel<<<dim3(64, 4), 256, SMEM_BYTES>>>();
    loss_kernel<<<1, 1024>>>(out);
}